// round 6
// baseline (speedup 1.0000x reference)
#include <cuda_runtime.h>
#include <cstdint>
#include <math.h>

#define Nb 512
#define Tt 64
#define Dd 512
#define Hh 512
#define FH 2048
#define NCTA 128

// Persistent state (device globals: no allocations allowed)
__device__ float g_h[2][Nb * Hh];
__device__ float g_c[2][Nb * Hh];
__device__ float g_attn[Nb * Hh];

// grid barrier state (sense-reversing; 128 barriers per launch -> returns to 0)
__device__ int g_bar_count = 0;
__device__ volatile int g_bar_flag = 0;

#define ASTR 20
#define BSTR 136
#define A_FLOATS (64 * ASTR)
#define STAGE_FLOATS (64 * ASTR + 16 * BSTR)  // 3456 floats
#define NSTAGES 3
#define ITERS 96

#define CP_ASYNC16(dst, src) \
    asm volatile("cp.async.cg.shared.global [%0], [%1], 16;\n" :: "r"(dst), "l"(src))
#define CP_COMMIT() asm volatile("cp.async.commit_group;\n")
#define CP_WAIT1()  asm volatile("cp.async.wait_group 1;\n")

__device__ __forceinline__ uint32_t smem_u32(const void* p) {
    return (uint32_t)__cvta_generic_to_shared(p);
}

__global__ __launch_bounds__(256, 1) void fused_lstm_kernel(
    const float* __restrict__ x, const float* __restrict__ A,
    const float* __restrict__ Wx, const float* __restrict__ Wh,
    const float* __restrict__ Wattn, const float* __restrict__ bias,
    float* __restrict__ out)
{
    __shared__ __align__(16) float sm[NSTAGES * STAGE_FLOATS];
    __shared__ float ared[8][16];
    __shared__ float aw[16];

    const int tid = threadIdx.x;
    const int bid = blockIdx.x;
    const int lane = tid & 31, warp = tid >> 5;

    // GEMM tile mapping (identical to the proven per-step kernel)
    const int j0 = (bid & 15) * 32;
    const int n0 = (bid >> 4) * 64;
    const int am = tid >> 2, akq = (tid & 3) * 4;
    const int wm = (tid >> 5) & 1, wn = tid >> 6;
    const int gid = lane >> 2, tg = lane & 3;

    int sense = 0;  // only tid 0's copy is used
    auto gbar = [&]() {
        __threadfence();
        __syncthreads();
        if (tid == 0) {
            sense ^= 1;
            if (atomicAdd(&g_bar_count, 1) == NCTA - 1) {
                atomicExch(&g_bar_count, 0);
                __threadfence();
                g_bar_flag = sense;
            } else {
                while (g_bar_flag != sense) __nanosleep(64);
            }
        }
        __syncthreads();
        __threadfence();
    };

    // ---------------- init: h0 = c0 = mean over 16 spatial positions -------
    {
#pragma unroll
        for (int rr = 0; rr < 4; rr++) {
            int n = bid * 4 + rr;
            const float4* abase = (const float4*)(A + (size_t)n * Hh * 16);
#pragma unroll
            for (int i = 0; i < 2; i++) {
                int r = tid + i * 256;
                float4 v0 = abase[r * 4 + 0], v1 = abase[r * 4 + 1];
                float4 v2 = abase[r * 4 + 2], v3 = abase[r * 4 + 3];
                float s = (v0.x + v0.y + v0.z + v0.w) + (v1.x + v1.y + v1.z + v1.w)
                        + (v2.x + v2.y + v2.z + v2.w) + (v3.x + v3.y + v3.z + v3.w);
                float m = s * (1.0f / 16.0f);
                g_h[0][n * Hh + r] = m;
                g_c[0][n * Hh + r] = m;
            }
        }
    }
    gbar();  // h0/c0 visible grid-wide

    for (int t = 0; t < Tt; t++) {
        const int pi = t & 1;
        const float* h_in = g_h[pi];
        const float* c_in = g_c[pi];
        float* h_out = g_h[pi ^ 1];
        float* c_out = g_c[pi ^ 1];

        // ---------------- attention phase: rows bid*4 .. bid*4+3 -----------
        {
            const float* hsrc = h_in;
#pragma unroll 1
            for (int rr = 0; rr < 4; rr++) {
                int n = bid * 4 + rr;
                const float4* abase = (const float4*)(A + (size_t)n * Hh * 16);
                float part[16];
#pragma unroll
                for (int p = 0; p < 16; p++) part[p] = 0.f;
#pragma unroll
                for (int i = 0; i < 2; i++) {
                    int r = tid + i * 256;
                    float hv = hsrc[n * Hh + r];
#pragma unroll
                    for (int q = 0; q < 4; q++) {
                        float4 v = abase[r * 4 + q];
                        part[q * 4 + 0] += hv * v.x;
                        part[q * 4 + 1] += hv * v.y;
                        part[q * 4 + 2] += hv * v.z;
                        part[q * 4 + 3] += hv * v.w;
                    }
                }
#pragma unroll
                for (int off = 16; off >= 1; off >>= 1)
#pragma unroll
                    for (int p = 0; p < 16; p++)
                        part[p] += __shfl_xor_sync(0xffffffffu, part[p], off);
                if (lane == 0) {
#pragma unroll
                    for (int p = 0; p < 16; p++) ared[warp][p] = part[p];
                }
                __syncthreads();
                if (tid == 0) {
                    const float scale = 0.044194173824159216f;  // 1/sqrt(512)
                    float sc[16];
                    float mx = -1e30f;
#pragma unroll
                    for (int p = 0; p < 16; p++) {
                        float s = 0.f;
#pragma unroll
                        for (int w8 = 0; w8 < 8; w8++) s += ared[w8][p];
                        sc[p] = s * scale;
                        mx = fmaxf(mx, sc[p]);
                    }
                    float s = 0.f;
#pragma unroll
                    for (int p = 0; p < 16; p++) { float e = expf(sc[p] - mx); aw[p] = e; s += e; }
                    float inv = 1.f / s;
#pragma unroll
                    for (int p = 0; p < 16; p++) aw[p] *= inv;
                }
                __syncthreads();
                float wl[16];
#pragma unroll
                for (int p = 0; p < 16; p++) wl[p] = aw[p];
#pragma unroll
                for (int i = 0; i < 2; i++) {
                    int r = tid + i * 256;
                    float s = 0.f;
#pragma unroll
                    for (int q = 0; q < 4; q++) {
                        float4 v = abase[r * 4 + q];  // L1-hot: second pass
                        s += v.x * wl[q * 4 + 0] + v.y * wl[q * 4 + 1]
                           + v.z * wl[q * 4 + 2] + v.w * wl[q * 4 + 3];
                    }
                    g_attn[n * Hh + r] = s;
                }
                __syncthreads();
            }
        }

        // ---------------- GEMM + gates phase --------------------------------
        const float* xbase = x + (size_t)n0 * Tt * Dd + (size_t)t * Dd;

        auto issue = [&](int i) {
            float* stg = sm + (i % NSTAGES) * STAGE_FLOATS;
            int seg = i >> 5;
            int kl = (i & 31) << 4;
            const float* Ab; size_t astr; const float* W;
            if (seg == 0)      { Ab = xbase;                        astr = (size_t)Tt * Dd; W = Wx; }
            else if (seg == 1) { Ab = h_in   + (size_t)n0 * Hh;     astr = Hh;              W = Wh; }
            else               { Ab = g_attn + (size_t)n0 * Hh;     astr = Hh;              W = Wattn; }
            const float* asrc = Ab + (size_t)am * astr + kl + akq;
            CP_ASYNC16(smem_u32(stg + am * ASTR + akq), asrc);
            float* Bst = stg + A_FLOATS;
#pragma unroll
            for (int j = 0; j < 2; j++) {
                int e = tid + j * 256;
                int k = e >> 5, n4 = e & 31;
                const float* bsrc = W + (size_t)(kl + k) * FH + (n4 >> 3) * 512 + j0 + (n4 & 7) * 4;
                CP_ASYNC16(smem_u32(Bst + k * BSTR + n4 * 4), bsrc);
            }
        };

        // Pre-issue the x-segment stages (no dependence on attn/h of this step)
        issue(0); CP_COMMIT();
        issue(1); CP_COMMIT();

        gbar();  // all CTAs' attn + previous h/c visible before consuming

        float acc[2][4][4];
#pragma unroll
        for (int fm = 0; fm < 2; fm++)
#pragma unroll
            for (int fn = 0; fn < 4; fn++)
#pragma unroll
                for (int e = 0; e < 4; e++) acc[fm][fn][e] = 0.f;

        for (int i = 0; i < ITERS; i++) {
            CP_WAIT1();
            __syncthreads();
            const float* As = sm + (i % NSTAGES) * STAGE_FLOATS;
            const float* Bs = As + A_FLOATS;
#pragma unroll
            for (int k8 = 0; k8 < 2; k8++) {
                int kb = k8 * 8;
                uint32_t a[2][4], bf[4][2];
#pragma unroll
                for (int fm = 0; fm < 2; fm++) {
                    int row = wm * 32 + fm * 16 + gid;
                    a[fm][0] = __float_as_uint(As[row * ASTR + kb + tg]);
                    a[fm][1] = __float_as_uint(As[(row + 8) * ASTR + kb + tg]);
                    a[fm][2] = __float_as_uint(As[row * ASTR + kb + tg + 4]);
                    a[fm][3] = __float_as_uint(As[(row + 8) * ASTR + kb + tg + 4]);
                }
#pragma unroll
                for (int fn = 0; fn < 4; fn++) {
                    int col = wn * 32 + fn * 8 + gid;
                    bf[fn][0] = __float_as_uint(Bs[(kb + tg) * BSTR + col]);
                    bf[fn][1] = __float_as_uint(Bs[(kb + tg + 4) * BSTR + col]);
                }
#pragma unroll
                for (int fm = 0; fm < 2; fm++)
#pragma unroll
                    for (int fn = 0; fn < 4; fn++) {
                        asm volatile(
                            "mma.sync.aligned.m16n8k8.row.col.f32.tf32.tf32.f32 "
                            "{%0,%1,%2,%3}, {%4,%5,%6,%7}, {%8,%9}, {%0,%1,%2,%3};\n"
                            : "+f"(acc[fm][fn][0]), "+f"(acc[fm][fn][1]),
                              "+f"(acc[fm][fn][2]), "+f"(acc[fm][fn][3])
                            : "r"(a[fm][0]), "r"(a[fm][1]), "r"(a[fm][2]), "r"(a[fm][3]),
                              "r"(bf[fn][0]), "r"(bf[fn][1]));
                    }
            }
            if (i + 2 < ITERS) issue(i + 2);
            CP_COMMIT();
        }

        __syncthreads();
        // stash a-tile (64 x 128) in smem for gate gathering
        float (*atile)[132] = (float(*)[132])sm;
#pragma unroll
        for (int fm = 0; fm < 2; fm++)
#pragma unroll
            for (int fn = 0; fn < 4; fn++) {
                int R = wm * 32 + fm * 16 + gid, C = wn * 32 + fn * 8 + tg * 2;
                atile[R][C]         = acc[fm][fn][0];
                atile[R][C + 1]     = acc[fm][fn][1];
                atile[R + 8][C]     = acc[fm][fn][2];
                atile[R + 8][C + 1] = acc[fm][fn][3];
            }
        __syncthreads();

        {
            int col = tid & 31;
            int r0 = tid >> 5;
            float bi = bias[j0 + col];
            float bff = bias[512 + j0 + col];
            float bo = bias[1024 + j0 + col];
            float bg = bias[1536 + j0 + col];
#pragma unroll
            for (int q = 0; q < 8; q++) {
                int row = r0 + q * 8;
                float vi = atile[row][col]      + bi;
                float vf = atile[row][col + 32] + bff;
                float vo = atile[row][col + 64] + bo;
                float vg = atile[row][col + 96] + bg;
                float ig = 1.f / (1.f + expf(-vi));
                float fg = 1.f / (1.f + expf(-vf));
                float og = 1.f / (1.f + expf(-vo));
                float gg = tanhf(vg);
                int n = n0 + row, hc = j0 + col;
                float cold = c_in[n * Hh + hc];
                float cn = fg * cold + ig * gg;
                float hn = og * tanhf(cn);
                c_out[n * Hh + hc] = cn;
                h_out[n * Hh + hc] = hn;
                out[((size_t)n * Tt + t) * Hh + hc] = hn;
            }
        }

        if (t < Tt - 1) gbar();  // publish h/c for next step's attention
        // total barriers per launch: 1 + 64 + 63 = 128 (even -> flag resets)
    }
}

// ---------------------------------------------------------------------------
extern "C" void kernel_launch(void* const* d_in, const int* in_sizes, int n_in,
                              void* d_out, int out_size) {
    const float* x     = (const float*)d_in[0];
    const float* A     = (const float*)d_in[1];
    const float* Wx    = (const float*)d_in[2];
    const float* Wh    = (const float*)d_in[3];
    const float* Wattn = (const float*)d_in[4];
    const float* b     = (const float*)d_in[5];
    float* out = (float*)d_out;

    fused_lstm_kernel<<<NCTA, 256>>>(x, A, Wx, Wh, Wattn, b, out);
}